// round 11
// baseline (speedup 1.0000x reference)
#include <cuda_runtime.h>
#include <cuda_bf16.h>
#include <math.h>
#include <stdint.h>

// Problem constants
#define B_  2
#define S_  2048
#define HID 2048
#define NH  16
#define NKV 4
#define DH  128
#define MROWS (B_ * S_)        // 4096
#define EPS 1e-6f

// packed QKV col layout: [ Q(0..2047) | K(2048..2559) | V(2560..3071) ]
#define QKVS 3072
#define KOFF 2048
#define VOFF 2560

// 1/sqrt(DH) * log2(e): folded into Q in the fused epilogue; softmax uses exp2f.
#define SCL2E (0.08838834764831845f * 1.4426950408889634f)

// K-dim fragment interleave: within each 8-group, q -> 2*(q&3) + (q>>2).
__device__ __host__ __forceinline__ int perm8(int q) { return 2 * (q & 3) + (q >> 2); }

// ---------------- scratch ----------------
__device__ float g_X   [(size_t)MROWS * HID];        // Xr (K-permuted input)
__device__ float g_Qp  [(size_t)MROWS * HID];        // Q, rms+rope'd, d-permuted, prescaled
__device__ float g_Kp  [(size_t)MROWS * NKV * DH];   // K, rms+rope'd, d-permuted
__device__ float g_Vt  [(size_t)B_ * NKV * DH * S_]; // [b][kvh][d][s'], s-permuted, tf32
__device__ float g_O   [(size_t)MROWS * NH * DH];    // flash out, d-permuted
__device__ float g_WqkvT[(size_t)QKVS * HID];        // [N=3072][K=2048], K-permuted
__device__ float g_WoT [(size_t)NH * DH * HID];      // [N=2048][K=2048], K-permuted

// ---------------- helpers ----------------
__device__ __forceinline__ uint32_t smem_u32(const void* p) {
    uint32_t a;
    asm("{ .reg .u64 t; cvta.to.shared.u64 t, %1; cvt.u32.u64 %0, t; }" : "=r"(a) : "l"(p));
    return a;
}
__device__ __forceinline__ float tf32r(float x) {
    uint32_t r;
    asm("cvt.rna.tf32.f32 %0, %1;" : "=r"(r) : "f"(x));
    return __uint_as_float(r);
}
#define CP_ASYNC16(sdst, gsrc) \
    asm volatile("cp.async.cg.shared.global [%0], [%1], 16;" :: "r"(sdst), "l"(gsrc))
#define CP_COMMIT() asm volatile("cp.async.commit_group;" ::: "memory")
#define CP_WAIT(n)  asm volatile("cp.async.wait_group %0;" :: "n"(n) : "memory")

__device__ __forceinline__ void mma_tf32(float& c0, float& c1, float& c2, float& c3,
                                         uint32_t a0, uint32_t a1, uint32_t a2, uint32_t a3,
                                         uint32_t b0, uint32_t b1) {
    asm volatile(
        "mma.sync.aligned.m16n8k8.row.col.f32.tf32.tf32.f32 "
        "{%0,%1,%2,%3}, {%4,%5,%6,%7}, {%8,%9}, {%0,%1,%2,%3};"
        : "+f"(c0), "+f"(c1), "+f"(c2), "+f"(c3)
        : "r"(a0), "r"(a1), "r"(a2), "r"(a3), "r"(b0), "r"(b1));
}

// ---------------- X: tf32 round + K-dim interleave ----------------
__global__ void __launch_bounds__(256) xperm_tf32_kernel(float* __restrict__ dst,
                                                         const float* __restrict__ src,
                                                         size_t n8) {
    for (size_t i = blockIdx.x * blockDim.x + threadIdx.x; i < n8;
         i += (size_t)gridDim.x * blockDim.x) {
        float4 lo = ((const float4*)src)[i * 2];
        float4 hi = ((const float4*)src)[i * 2 + 1];
        float4 o0 = make_float4(tf32r(lo.x), tf32r(hi.x), tf32r(lo.y), tf32r(hi.y));
        float4 o1 = make_float4(tf32r(lo.z), tf32r(hi.z), tf32r(lo.w), tf32r(hi.w));
        ((float4*)dst)[i * 2]     = o0;
        ((float4*)dst)[i * 2 + 1] = o1;
    }
}

// ---------------- transpose + tf32 round + K-permute ----------------
__global__ void __launch_bounds__(256) transpose_tf32_kernel(float* __restrict__ dst,
                                                             const float* __restrict__ src,
                                                             int R, int C) {
    __shared__ float t[32][33];
    int bx = blockIdx.x * 32;
    int by = blockIdx.y * 32;
    int tx = threadIdx.x, ty = threadIdx.y;
#pragma unroll
    for (int i = 0; i < 4; i++)
        t[ty + i * 8][tx] = src[(size_t)(by + ty + i * 8) * C + bx + tx];
    __syncthreads();
    int px = (tx & 24) + perm8(tx & 7);
#pragma unroll
    for (int i = 0; i < 4; i++)
        dst[(size_t)(bx + ty + i * 8) * R + by + px] = tf32r(t[tx][ty + i * 8]);
}

// ---------------- GEMM common pieces ----------------
#define GK      2048
#define GM_BM   128
#define GM_BN   128
#define GM_BK   16
#define GM_LDS  24
#define GM_NST  3
#define GM_NIT  (GK / GM_BK)
#define GM_STAGE_FLOATS (2 * 128 * GM_LDS)   // 6144
#define GM_SMEM_BYTES (GM_NST * GM_STAGE_FLOATS * 4)   // 73728

__device__ __forceinline__ void gm_load_stage(uint32_t sA, uint32_t sB,
                                              const float* __restrict__ Atile,
                                              const float* __restrict__ Btile,
                                              int tid) {
#pragma unroll
    for (int i = 0; i < 2; i++) {
        int idx = i * 256 + tid;
        int r = idx >> 2, c = idx & 3;
        CP_ASYNC16(sA + (uint32_t)(r * (GM_LDS * 4) + c * 16),
                   Atile + (size_t)r * GK + c * 4);
    }
#pragma unroll
    for (int i = 0; i < 2; i++) {
        int idx = i * 256 + tid;
        int r = idx >> 2, c = idx & 3;
        CP_ASYNC16(sB + (uint32_t)(r * (GM_LDS * 4) + c * 16),
                   Btile + (size_t)r * GK + c * 4);
    }
    CP_COMMIT();
}

// Mainloop as a macro body via inline function pattern: computes acc for this CTA tile.
__device__ __forceinline__ void gm_mainloop(
    float acc[2][8][4], float* gsm, uint32_t sbase,
    const float* Abase, const float* Bbase,
    int tid, int wm, int wn, int gid, int tig)
{
    uint32_t stA[GM_NST], stB[GM_NST];
#pragma unroll
    for (int s = 0; s < GM_NST; s++) {
        stA[s] = sbase + (uint32_t)(s * GM_STAGE_FLOATS * 4);
        stB[s] = stA[s] + 128u * GM_LDS * 4u;
    }
    gm_load_stage(stA[0], stB[0], Abase, Bbase, tid);
    gm_load_stage(stA[1], stB[1], Abase + GM_BK, Bbase + GM_BK, tid);

    for (int it = 0; it < GM_NIT; it++) {
        CP_WAIT(1);
        __syncthreads();

        const int ki = it + 2;
        if (ki < GM_NIT) {
            const int b = ki % GM_NST;
            gm_load_stage(stA[b], stB[b], Abase + ki * GM_BK, Bbase + ki * GM_BK, tid);
        }

        const int s = it % GM_NST;
        const float* As0 = gsm + (size_t)s * GM_STAGE_FLOATS;
        const float* Bs0 = As0 + 128 * GM_LDS;

#pragma unroll
        for (int k0 = 0; k0 < GM_BK; k0 += 8) {
            uint32_t af[2][4];
#pragma unroll
            for (int mt = 0; mt < 2; mt++) {
                int r = wm * 32 + mt * 16 + gid;
                float2 aA = *(const float2*)(As0 + r * GM_LDS + k0 + 2 * tig);
                float2 aB = *(const float2*)(As0 + (r + 8) * GM_LDS + k0 + 2 * tig);
                af[mt][0] = __float_as_uint(aA.x);
                af[mt][1] = __float_as_uint(aB.x);
                af[mt][2] = __float_as_uint(aA.y);
                af[mt][3] = __float_as_uint(aB.y);
            }
#pragma unroll
            for (int nt = 0; nt < 8; nt++) {
                int rn = wn * 64 + nt * 8 + gid;
                float2 bv = *(const float2*)(Bs0 + rn * GM_LDS + k0 + 2 * tig);
#pragma unroll
                for (int mt = 0; mt < 2; mt++)
                    mma_tf32(acc[mt][nt][0], acc[mt][nt][1], acc[mt][nt][2], acc[mt][nt][3],
                             af[mt][0], af[mt][1], af[mt][2], af[mt][3],
                             __float_as_uint(bv.x), __float_as_uint(bv.y));
            }
        }
    }
}

// ---------------- plain GEMM (O-projection) ----------------
__global__ void __launch_bounds__(256, 1) gemm_tf32mma_kernel(
    const float* __restrict__ A, const float* __restrict__ Bt,
    float* __restrict__ C, int M, int N)
{
    extern __shared__ float gsm[];
    const uint32_t sbase = smem_u32(gsm);
    const int tid = threadIdx.x;
    const int wid = tid >> 5, lid = tid & 31;
    const int wm = wid >> 1, wn = wid & 1;
    const int gid = lid >> 2, tig = lid & 3;
    const int bm = blockIdx.y * GM_BM;
    const int bn = blockIdx.x * GM_BN;

    float acc[2][8][4];
#pragma unroll
    for (int mt = 0; mt < 2; mt++)
#pragma unroll
        for (int nt = 0; nt < 8; nt++)
#pragma unroll
            for (int q = 0; q < 4; q++) acc[mt][nt][q] = 0.f;

    gm_mainloop(acc, gsm, sbase, A + (size_t)bm * GK, Bt + (size_t)bn * GK,
                tid, wm, wn, gid, tig);

#pragma unroll
    for (int mt = 0; mt < 2; mt++) {
        int r0 = bm + wm * 32 + mt * 16 + gid;
#pragma unroll
        for (int nt = 0; nt < 8; nt++) {
            int c = bn + wn * 64 + nt * 8 + tig * 2;
            *(float2*)(C + (size_t)r0 * N + c) = make_float2(acc[mt][nt][0], acc[mt][nt][1]);
            *(float2*)(C + (size_t)(r0 + 8) * N + c) = make_float2(acc[mt][nt][2], acc[mt][nt][3]);
        }
    }
}

// ---------------- QKV GEMM with fused RMSNorm+RoPE (Q,K) / transpose (V) epilogue ----------
__global__ void __launch_bounds__(256, 1) gemm_qkv_fused_kernel(
    const float* __restrict__ A, const float* __restrict__ Bt,
    float* __restrict__ Qp, float* __restrict__ Kp, float* __restrict__ Vt,
    const float* __restrict__ qnw, const float* __restrict__ knw,
    const float* __restrict__ cosb, const float* __restrict__ sinb)
{
    extern __shared__ float gsm[];
    const uint32_t sbase = smem_u32(gsm);
    const int tid = threadIdx.x;
    const int wid = tid >> 5, lid = tid & 31;
    const int wm = wid >> 1, wn = wid & 1;
    const int gid = lid >> 2, tig = lid & 3;
    const int bm = blockIdx.y * GM_BM;
    const int bn = blockIdx.x * GM_BN;

    float acc[2][8][4];
#pragma unroll
    for (int mt = 0; mt < 2; mt++)
#pragma unroll
        for (int nt = 0; nt < 8; nt++)
#pragma unroll
            for (int q = 0; q < 4; q++) acc[mt][nt][q] = 0.f;

    gm_mainloop(acc, gsm, sbase, A + (size_t)bm * GK, Bt + (size_t)bn * GK,
                tid, wm, wn, gid, tig);

    __syncthreads();     // all warps done reading mainloop stages before smem reuse

    if (bn < VOFF) {
        // ---- Q or K head tile: RMSNorm + RoPE + tf32 + d-permute ----
        const bool isQ = (bn < KOFF);
        const float* wptr = isQ ? qnw : knw;
        const float oscale = isQ ? SCL2E : 1.0f;
        float* outb = isQ ? (Qp + bn) : (Kp + (bn - KOFF));
        const int ostr = isQ ? HID : (NKV * DH);

        float* Ns = gsm;                 // [128][136] weighted-normalized values
        float* sums2 = gsm + 128 * 136;  // [2][128] per-warp-half row sums

        // 1) partial row sums of squares
#pragma unroll
        for (int mt = 0; mt < 2; mt++) {
            float s1 = 0.f, s2 = 0.f;
#pragma unroll
            for (int nt = 0; nt < 8; nt++) {
                s1 += acc[mt][nt][0] * acc[mt][nt][0] + acc[mt][nt][1] * acc[mt][nt][1];
                s2 += acc[mt][nt][2] * acc[mt][nt][2] + acc[mt][nt][3] * acc[mt][nt][3];
            }
            s1 += __shfl_xor_sync(0xffffffffu, s1, 1);
            s1 += __shfl_xor_sync(0xffffffffu, s1, 2);
            s2 += __shfl_xor_sync(0xffffffffu, s2, 1);
            s2 += __shfl_xor_sync(0xffffffffu, s2, 2);
            if (tig == 0) {
                int r = wm * 32 + mt * 16 + gid;
                sums2[wn * 128 + r] = s1;
                sums2[wn * 128 + r + 8] = s2;
            }
        }
        __syncthreads();

        float inv[2][2];
#pragma unroll
        for (int mt = 0; mt < 2; mt++)
#pragma unroll
            for (int rg = 0; rg < 2; rg++) {
                int r = wm * 32 + mt * 16 + gid + rg * 8;
                inv[mt][rg] = rsqrtf((sums2[r] + sums2[128 + r]) * (1.0f / DH) + EPS);
            }
        __syncthreads();   // sums read before Ns overwrites smem

        // 2) stage weighted-normalized values (and keep in acc)
#pragma unroll
        for (int mt = 0; mt < 2; mt++) {
            int r1 = wm * 32 + mt * 16 + gid, r2 = r1 + 8;
#pragma unroll
            for (int nt = 0; nt < 8; nt++) {
                int c = wn * 64 + nt * 8 + 2 * tig;
                float2 w2 = *(const float2*)(wptr + c);
                float n0 = acc[mt][nt][0] * inv[mt][0] * w2.x;
                float n1 = acc[mt][nt][1] * inv[mt][0] * w2.y;
                float n2 = acc[mt][nt][2] * inv[mt][1] * w2.x;
                float n3 = acc[mt][nt][3] * inv[mt][1] * w2.y;
                *(float2*)(Ns + r1 * 136 + c) = make_float2(n0, n1);
                *(float2*)(Ns + r2 * 136 + c) = make_float2(n2, n3);
                acc[mt][nt][0] = n0; acc[mt][nt][1] = n1;
                acc[mt][nt][2] = n2; acc[mt][nt][3] = n3;
            }
        }
        __syncthreads();

        // 3) rope combine with partner column c^64, write tf32 d-permuted
        const float sgn = (wn == 0) ? -1.f : 1.f;
        const int dpl0 = perm8(2 * tig);
        const int dpl1 = perm8(2 * tig + 1);
#pragma unroll
        for (int mt = 0; mt < 2; mt++) {
            int r1 = wm * 32 + mt * 16 + gid, r2 = r1 + 8;
            int s1row = (bm + r1) & (S_ - 1);
            int s2row = s1row + 8;
#pragma unroll
            for (int nt = 0; nt < 8; nt++) {
                int c = wn * 64 + nt * 8 + 2 * tig;
                int pc = c ^ 64;
                float2 p1 = *(const float2*)(Ns + r1 * 136 + pc);
                float2 p2 = *(const float2*)(Ns + r2 * 136 + pc);
                float2 cs1 = *(const float2*)(cosb + (size_t)s1row * DH + c);
                float2 sn1 = *(const float2*)(sinb + (size_t)s1row * DH + c);
                float2 cs2 = *(const float2*)(cosb + (size_t)s2row * DH + c);
                float2 sn2 = *(const float2*)(sinb + (size_t)s2row * DH + c);
                float o0 = acc[mt][nt][0] * cs1.x + sgn * p1.x * sn1.x;
                float o1 = acc[mt][nt][1] * cs1.y + sgn * p1.y * sn1.y;
                float o2 = acc[mt][nt][2] * cs2.x + sgn * p2.x * sn2.x;
                float o3 = acc[mt][nt][3] * cs2.y + sgn * p2.y * sn2.y;
                int cb = c & ~7;
                size_t g1 = (size_t)(bm + r1) * ostr;
                size_t g2 = (size_t)(bm + r2) * ostr;
                outb[g1 + cb + dpl0] = tf32r(o0 * oscale);
                outb[g1 + cb + dpl1] = tf32r(o1 * oscale);
                outb[g2 + cb + dpl0] = tf32r(o2 * oscale);
                outb[g2 + cb + dpl1] = tf32r(o3 * oscale);
            }
        }
    } else {
        // ---- V head tile: tf32 round + transpose to [d][s'] ----
        float* Cs = gsm;    // [d=128][s=128] stride 136
#pragma unroll
        for (int mt = 0; mt < 2; mt++) {
            int r1 = wm * 32 + mt * 16 + gid, r2 = r1 + 8;
#pragma unroll
            for (int nt = 0; nt < 8; nt++) {
                int c = wn * 64 + nt * 8 + 2 * tig;
                Cs[c * 136 + r1]       = tf32r(acc[mt][nt][0]);
                Cs[(c + 1) * 136 + r1] = tf32r(acc[mt][nt][1]);
                Cs[c * 136 + r2]       = tf32r(acc[mt][nt][2]);
                Cs[(c + 1) * 136 + r2] = tf32r(acc[mt][nt][3]);
            }
        }
        __syncthreads();

        const int kvh = (bn - VOFF) >> 7;
        const int bb = bm >> 11;                     // batch index
        const int s0 = bm & (S_ - 1);
        float* vb = Vt + ((size_t)(bb * NKV + kvh) * DH) * S_;
#pragma unroll
        for (int t = 0; t < 64; t++) {
            int i = tid + t * 256;
            int d = i >> 7, sl = i & 127;
            int sp = (sl & ~7) + perm8(sl & 7);
            vb[(size_t)d * S_ + s0 + sp] = Cs[d * 136 + sl];
        }
    }
}

// ---------------- tensor-core flash attention v4 (unchanged) ----------------
#define FKP 136
#define FVP 72
#define FQ_OFF 0
#define FK_OFF (128 * FKP)
#define FV_OFF (FK_OFF + 2 * 64 * FKP)
#define FT_FLOATS (FV_OFF + 2 * 128 * FVP)
#define FT_BYTES (FT_FLOATS * 4)             // 212992

__global__ void __launch_bounds__(256, 1) flash_tc4_kernel(
    const float* __restrict__ Qp, const float* __restrict__ Kp,
    const float* __restrict__ Vt, float* __restrict__ Og)
{
    extern __shared__ float fsm[];
    const uint32_t sb = smem_u32(fsm);

    const int qt  = (int)gridDim.x - 1 - (int)blockIdx.x;
    const int h   = blockIdx.y;
    const int b   = blockIdx.z;
    const int kvh = h >> 2;
    const int tid = threadIdx.x;
    const int wid = tid >> 5, lid = tid & 31;
    const int gid = lid >> 2, tig = lid & 3;

    const int r1loc = wid * 16 + gid;
    const int r2loc = r1loc + 8;
    const int r1g = qt * 128 + r1loc;
    const int r2g = r1g + 8;

    const float* Kbase  = Kp + (size_t)(b * S_) * (NKV * DH) + (size_t)kvh * DH;
    const float* Vtbase = Vt + ((size_t)(b * NKV + kvh) * DH) * S_;

    {
        const float* Qb = Qp + (size_t)(b * S_ + qt * 128) * HID + (size_t)h * DH;
#pragma unroll
        for (int t = 0; t < 16; t++) {
            int i = tid + t * 256;
            int m = i >> 5, c = i & 31;
            CP_ASYNC16(sb + (uint32_t)((FQ_OFF + m * FKP + c * 4) * 4),
                       Qb + (size_t)m * HID + c * 4);
        }
    }
#pragma unroll
    for (int t = 0; t < 8; t++) {
        int i = tid + t * 256;
        int n = i >> 5, c = i & 31;
        CP_ASYNC16(sb + (uint32_t)((FK_OFF + n * FKP + c * 4) * 4),
                   Kbase + (size_t)n * (NKV * DH) + c * 4);
    }
#pragma unroll
    for (int t = 0; t < 8; t++) {
        int i = tid + t * 256;
        int d = i >> 4, c = i & 15;
        CP_ASYNC16(sb + (uint32_t)((FV_OFF + d * FVP + c * 4) * 4),
                   Vtbase + (size_t)d * S_ + c * 4);
    }
    CP_COMMIT();

    float oacc[16][4];
#pragma unroll
    for (int db = 0; db < 16; db++)
#pragma unroll
        for (int q = 0; q < 4; q++) oacc[db][q] = 0.f;
    float m1 = -1e30f, m2 = -1e30f, l1 = 0.f, l2 = 0.f;

    const int ntiles = 2 * qt + 2;
    for (int j = 0; j < ntiles; j++) {
        CP_WAIT(0);
        __syncthreads();

        if (j + 1 < ntiles) {
            const int nb_ = (j + 1) & 1;
            const uint32_t kd = sb + (uint32_t)((FK_OFF + nb_ * 64 * FKP) * 4);
            const uint32_t vd = sb + (uint32_t)((FV_OFF + nb_ * 128 * FVP) * 4);
#pragma unroll
            for (int t = 0; t < 8; t++) {
                int i = tid + t * 256;
                int n = i >> 5, c = i & 31;
                CP_ASYNC16(kd + (uint32_t)((n * FKP + c * 4) * 4),
                           Kbase + (size_t)((j + 1) * 64 + n) * (NKV * DH) + c * 4);
            }
#pragma unroll
            for (int t = 0; t < 8; t++) {
                int i = tid + t * 256;
                int d = i >> 4, c = i & 15;
                CP_ASYNC16(vd + (uint32_t)((d * FVP + c * 4) * 4),
                           Vtbase + (size_t)d * S_ + (j + 1) * 64 + c * 4);
            }
            CP_COMMIT();
        }

        const float* Qsb = fsm;
        const float* Ksb = fsm + FK_OFF + (j & 1) * 64 * FKP;
        const float* Vsb = fsm + FV_OFF + (j & 1) * 128 * FVP;

        float sacc[8][4];
#pragma unroll
        for (int nb = 0; nb < 8; nb++)
#pragma unroll
            for (int q = 0; q < 4; q++) sacc[nb][q] = 0.f;

#pragma unroll
        for (int ks = 0; ks < 16; ks++) {
            int k0 = ks * 8;
            float2 qa = *(const float2*)(Qsb + r1loc * FKP + k0 + 2 * tig);
            float2 qb = *(const float2*)(Qsb + r2loc * FKP + k0 + 2 * tig);
            uint32_t a0 = __float_as_uint(qa.x);
            uint32_t a1 = __float_as_uint(qb.x);
            uint32_t a2 = __float_as_uint(qa.y);
            uint32_t a3 = __float_as_uint(qb.y);
#pragma unroll
            for (int nb = 0; nb < 8; nb++) {
                float2 kv2 = *(const float2*)(Ksb + (nb * 8 + gid) * FKP + k0 + 2 * tig);
                mma_tf32(sacc[nb][0], sacc[nb][1], sacc[nb][2], sacc[nb][3],
                         a0, a1, a2, a3,
                         __float_as_uint(kv2.x), __float_as_uint(kv2.y));
            }
        }

        if (j >= 2 * qt) {
#pragma unroll
            for (int nb = 0; nb < 8; nb++) {
                int c0g = j * 64 + nb * 8 + tig * 2;
                if (c0g > r1g)     sacc[nb][0] = -1e30f;
                if (c0g + 1 > r1g) sacc[nb][1] = -1e30f;
                if (c0g > r2g)     sacc[nb][2] = -1e30f;
                if (c0g + 1 > r2g) sacc[nb][3] = -1e30f;
            }
        }

        float mx1 = -1e30f, mx2 = -1e30f;
#pragma unroll
        for (int nb = 0; nb < 8; nb++) {
            mx1 = fmaxf(mx1, fmaxf(sacc[nb][0], sacc[nb][1]));
            mx2 = fmaxf(mx2, fmaxf(sacc[nb][2], sacc[nb][3]));
        }
        mx1 = fmaxf(mx1, __shfl_xor_sync(0xffffffffu, mx1, 1));
        mx1 = fmaxf(mx1, __shfl_xor_sync(0xffffffffu, mx1, 2));
        mx2 = fmaxf(mx2, __shfl_xor_sync(0xffffffffu, mx2, 1));
        mx2 = fmaxf(mx2, __shfl_xor_sync(0xffffffffu, mx2, 2));

        float mn1 = fmaxf(m1, mx1), mn2 = fmaxf(m2, mx2);
        const bool changed = (mn1 != m1) | (mn2 != m2);
        const bool any_changed = __any_sync(0xffffffffu, changed);
        float f1 = 1.f, f2 = 1.f;
        if (any_changed) {
            f1 = exp2f(m1 - mn1);
            f2 = exp2f(m2 - mn2);
        }
        m1 = mn1; m2 = mn2;

        float ls1 = 0.f, ls2 = 0.f;
#pragma unroll
        for (int nb = 0; nb < 8; nb++) {
            float p0 = tf32r(exp2f(sacc[nb][0] - mn1));
            float p1 = tf32r(exp2f(sacc[nb][1] - mn1));
            float p2 = tf32r(exp2f(sacc[nb][2] - mn2));
            float p3 = tf32r(exp2f(sacc[nb][3] - mn2));
            sacc[nb][0] = p0; sacc[nb][1] = p1;
            sacc[nb][2] = p2; sacc[nb][3] = p3;
            ls1 += p0 + p1;
            ls2 += p2 + p3;
        }
        ls1 += __shfl_xor_sync(0xffffffffu, ls1, 1);
        ls1 += __shfl_xor_sync(0xffffffffu, ls1, 2);
        ls2 += __shfl_xor_sync(0xffffffffu, ls2, 1);
        ls2 += __shfl_xor_sync(0xffffffffu, ls2, 2);

        if (any_changed) {
            l1 = l1 * f1 + ls1;
            l2 = l2 * f2 + ls2;
#pragma unroll
            for (int db = 0; db < 16; db++) {
                oacc[db][0] *= f1; oacc[db][1] *= f1;
                oacc[db][2] *= f2; oacc[db][3] *= f2;
            }
        } else {
            l1 += ls1;
            l2 += ls2;
        }

        const int s2 = tig >> 1;
        const bool odd = (tig & 1);
#pragma unroll
        for (int ks = 0; ks < 8; ks++) {
            float e, o;
            e = __shfl_sync(0xffffffffu, sacc[ks][0], s2, 4);
            o = __shfl_sync(0xffffffffu, sacc[ks][1], s2, 4);
            float a0f = odd ? o : e;
            e = __shfl_sync(0xffffffffu, sacc[ks][0], s2 + 2, 4);
            o = __shfl_sync(0xffffffffu, sacc[ks][1], s2 + 2, 4);
            float a2f = odd ? o : e;
            e = __shfl_sync(0xffffffffu, sacc[ks][2], s2, 4);
            o = __shfl_sync(0xffffffffu, sacc[ks][3], s2, 4);
            float a1f = odd ? o : e;
            e = __shfl_sync(0xffffffffu, sacc[ks][2], s2 + 2, 4);
            o = __shfl_sync(0xffffffffu, sacc[ks][3], s2 + 2, 4);
            float a3f = odd ? o : e;

            uint32_t a0 = __float_as_uint(a0f);
            uint32_t a1 = __float_as_uint(a1f);
            uint32_t a2 = __float_as_uint(a2f);
            uint32_t a3 = __float_as_uint(a3f);
            int k0 = ks * 8;
#pragma unroll
            for (int db = 0; db < 16; db++) {
                float2 vv = *(const float2*)(Vsb + (db * 8 + gid) * FVP + k0 + 2 * tig);
                mma_tf32(oacc[db][0], oacc[db][1], oacc[db][2], oacc[db][3],
                         a0, a1, a2, a3,
                         __float_as_uint(vv.x), __float_as_uint(vv.y));
            }
        }
    }

    const float inv1 = 1.0f / l1, inv2 = 1.0f / l2;
    const size_t obase = ((size_t)(b * S_ + qt * 128)) * (NH * DH) + (size_t)h * DH;
    const int p0 = perm8(2 * tig);
    const int p1 = perm8(2 * tig + 1);
#pragma unroll
    for (int db = 0; db < 16; db++) {
        float* o1p = Og + obase + (size_t)r1loc * (NH * DH) + db * 8;
        float* o2p = Og + obase + (size_t)r2loc * (NH * DH) + db * 8;
        o1p[p0] = tf32r(oacc[db][0] * inv1);
        o1p[p1] = tf32r(oacc[db][1] * inv1);
        o2p[p0] = tf32r(oacc[db][2] * inv2);
        o2p[p1] = tf32r(oacc[db][3] * inv2);
    }
}

// ---------------- launch ----------------
extern "C" void kernel_launch(void* const* d_in, const int* in_sizes, int n_in,
                              void* d_out, int out_size)
{
    const float* X    = (const float*)d_in[0];
    // d_in[1] = attention_mask: exact causal mask, applied analytically — unused
    const float* cosp = (const float*)d_in[2];
    const float* sinp = (const float*)d_in[3];
    const float* Wq   = (const float*)d_in[4];
    const float* Wk   = (const float*)d_in[5];
    const float* Wv   = (const float*)d_in[6];
    const float* Wo   = (const float*)d_in[7];
    const float* qnw  = (const float*)d_in[8];
    const float* knw  = (const float*)d_in[9];
    float* out = (float*)d_out;

    float *Xr, *Qp, *Kp, *VtP, *O, *WqkvT, *WoT;
    cudaGetSymbolAddress((void**)&Xr,    g_X);
    cudaGetSymbolAddress((void**)&Qp,    g_Qp);
    cudaGetSymbolAddress((void**)&Kp,    g_Kp);
    cudaGetSymbolAddress((void**)&VtP,   g_Vt);
    cudaGetSymbolAddress((void**)&O,     g_O);
    cudaGetSymbolAddress((void**)&WqkvT, g_WqkvT);
    cudaGetSymbolAddress((void**)&WoT,   g_WoT);

    cudaFuncSetAttribute(gemm_tf32mma_kernel, cudaFuncAttributeMaxDynamicSharedMemorySize,
                         GM_SMEM_BYTES);
    cudaFuncSetAttribute(gemm_qkv_fused_kernel, cudaFuncAttributeMaxDynamicSharedMemorySize,
                         GM_SMEM_BYTES);
    cudaFuncSetAttribute(flash_tc4_kernel, cudaFuncAttributeMaxDynamicSharedMemorySize,
                         FT_BYTES);

    // X: tf32 round + K-permute; weights: transpose + round + K-permute
    xperm_tf32_kernel<<<2048, 256>>>(Xr, X, (size_t)MROWS * HID / 8);
    transpose_tf32_kernel<<<dim3((NH * DH) / 32, HID / 32), dim3(32, 8)>>>(
        WqkvT, Wq, HID, NH * DH);
    transpose_tf32_kernel<<<dim3((NKV * DH) / 32, HID / 32), dim3(32, 8)>>>(
        WqkvT + (size_t)KOFF * HID, Wk, HID, NKV * DH);
    transpose_tf32_kernel<<<dim3((NKV * DH) / 32, HID / 32), dim3(32, 8)>>>(
        WqkvT + (size_t)VOFF * HID, Wv, HID, NKV * DH);
    transpose_tf32_kernel<<<dim3(HID / 32, (NH * DH) / 32), dim3(32, 8)>>>(
        WoT, Wo, NH * DH, HID);

    // Fused QKV projection + RMSNorm/RoPE/permutes: one kernel
    gemm_qkv_fused_kernel<<<dim3(QKVS / GM_BN, MROWS / GM_BM), 256, GM_SMEM_BYTES>>>(
        Xr, WqkvT, Qp, Kp, VtP, qnw, knw, cosp, sinp);

    // Flash attention v4
    flash_tc4_kernel<<<dim3(S_ / 128, NH, B_), 256, FT_BYTES>>>(Qp, Kp, VtP, O);

    // O-projection
    gemm_tf32mma_kernel<<<dim3(HID / GM_BN, MROWS / GM_BM), 256, GM_SMEM_BYTES>>>(
        O, WoT, out, MROWS, HID);
}